// round 2
// baseline (speedup 1.0000x reference)
#include <cuda_runtime.h>
#include <cstdint>

// Problem constants: b=1, n=4 views, f=8 frames, l=256, C=320, H=8, D=40.
#define C       320
#define L       1024
#define H       8
#define D       40
#define BFRM    8
#define ROWS    (BFRM * L)   // 8192

// ---- scratch (no allocations allowed) ----
__device__ float g_Q   [ROWS * C];
__device__ float g_K   [ROWS * C];
__device__ float g_V   [ROWS * C];
__device__ float g_Qi  [ROWS * C];
__device__ float g_base[ROWS * C];
__device__ float g_iat [ROWS * C];
__device__ float g_tmp [ROWS * C];

// logical row (bf*1024 + n*256 + l) -> hidden row ((n*8+bf)*256 + l)
__device__ __forceinline__ int hidden_row(int g) {
    int bf = g >> 10;
    int r  = g & 1023;
    int n  = r >> 8;
    int l  = r & 255;
    return ((n << 3) + bf) * 256 + l;
}

// ============================================================================
// tf32 helpers
// ============================================================================
__device__ __forceinline__ uint32_t tf32_of(float x) {
    uint32_t r;
    asm("cvt.rna.tf32.f32 %0, %1;" : "=r"(r) : "f"(x));
    return r;
}
// split x into tf32 hi + tf32 lo (returned as float-typed bit patterns)
__device__ __forceinline__ float tf32_split(float x, float& lo) {
    uint32_t hb = tf32_of(x);
    float hf = __uint_as_float(hb);
    lo = __uint_as_float(tf32_of(x - hf));
    return hf;
}

__device__ __forceinline__ void mma8(float d[4],
                                     uint32_t a0, uint32_t a1, uint32_t a2, uint32_t a3,
                                     uint32_t b0, uint32_t b1) {
    asm volatile(
        "mma.sync.aligned.m16n8k8.row.col.f32.tf32.tf32.f32 "
        "{%0,%1,%2,%3}, {%4,%5,%6,%7}, {%8,%9}, {%0,%1,%2,%3};"
        : "+f"(d[0]), "+f"(d[1]), "+f"(d[2]), "+f"(d[3])
        : "r"(a0), "r"(a1), "r"(a2), "r"(a3), "r"(b0), "r"(b1));
}

// ============================================================================
// Kernel 1: fused projection GEMM (Q, K, V, Q_i2v). 64x64 tile, BK=16.
// ============================================================================
__global__ __launch_bounds__(256) void proj_kernel(
    const float* __restrict__ hidden,
    const float* __restrict__ Wq, const float* __restrict__ Wk,
    const float* __restrict__ Wv, const float* __restrict__ Wqi)
{
    const float* W;
    float* Y;
    switch (blockIdx.z) {
        case 0:  W = Wq;  Y = g_Q;  break;
        case 1:  W = Wk;  Y = g_K;  break;
        case 2:  W = Wv;  Y = g_V;  break;
        default: W = Wqi; Y = g_Qi; break;
    }
    __shared__ float As[16][64];
    __shared__ float Bs[16][64];
    int t  = threadIdx.x;
    int m0 = blockIdx.x * 64, n0 = blockIdx.y * 64;
    int ty = t >> 4, tx = t & 15;
    int am = t >> 2, ak = (t & 3) * 4;
    const float* aptr = hidden + (size_t)hidden_row(m0 + am) * C;
    int nb = t & 63, kb = t >> 6;

    float acc[4][4];
#pragma unroll
    for (int i = 0; i < 4; i++)
#pragma unroll
        for (int j = 0; j < 4; j++) acc[i][j] = 0.f;

    for (int k0 = 0; k0 < C; k0 += 16) {
        float4 av = *(const float4*)(aptr + k0 + ak);
        As[ak    ][am] = av.x;
        As[ak + 1][am] = av.y;
        As[ak + 2][am] = av.z;
        As[ak + 3][am] = av.w;
#pragma unroll
        for (int i = 0; i < 4; i++)
            Bs[kb + 4 * i][nb] = W[(size_t)(k0 + kb + 4 * i) * C + n0 + nb];
        __syncthreads();
#pragma unroll
        for (int kk = 0; kk < 16; kk++) {
            float4 a = *(const float4*)&As[kk][ty * 4];
            float4 b = *(const float4*)&Bs[kk][tx * 4];
            acc[0][0] += a.x * b.x; acc[0][1] += a.x * b.y; acc[0][2] += a.x * b.z; acc[0][3] += a.x * b.w;
            acc[1][0] += a.y * b.x; acc[1][1] += a.y * b.y; acc[1][2] += a.y * b.z; acc[1][3] += a.y * b.w;
            acc[2][0] += a.z * b.x; acc[2][1] += a.z * b.y; acc[2][2] += a.z * b.z; acc[2][3] += a.z * b.w;
            acc[3][0] += a.w * b.x; acc[3][1] += a.w * b.y; acc[3][2] += a.w * b.z; acc[3][3] += a.w * b.w;
        }
        __syncthreads();
    }
#pragma unroll
    for (int i = 0; i < 4; i++) {
        float4 v = make_float4(acc[i][0], acc[i][1], acc[i][2], acc[i][3]);
        *(float4*)&Y[(size_t)(m0 + ty * 4 + i) * C + n0 + tx * 4] = v;
    }
}

// ============================================================================
// Kernel 2: flash attention with mma.sync tf32 (3xTF32 for fp32-grade accuracy)
// One launch covers base (i2v=0) and i2v (i2v=1) attention.
// Block: 128 thr = 4 warps, each warp 16 q-rows -> 64 q-rows/block.
// Key tiles of 64, K/V staged in smem as tf32 hi/lo.
// ============================================================================
#define KT        64
#define QT        64
#define KV_STRIDE 44   // floats per K/V smem row (bank-conflict-free B frags)
#define P_STRIDE  66   // floats per P smem row
#define SMEM_KV   (KT * KV_STRIDE)                 // 2816 floats per array
#define SMEM_ATTN ((4 * SMEM_KV + 4 * 16 * P_STRIDE) * 4)  // bytes = 61952

__global__ __launch_bounds__(128) void attn_mma_kernel()
{
    extern __shared__ float sm[];
    const int i2v = blockIdx.z >> 3;
    const int bf  = blockIdx.z & 7;
    const int h   = blockIdx.y;
    const int qt  = blockIdx.x;

    const float* Qsrc = i2v ? g_Qi : g_Q;
    float*       O    = i2v ? g_iat : g_base;
    const int kvbase  = i2v ? 0 : bf * L;

    const int tid  = threadIdx.x;
    const int w    = tid >> 5;
    const int lane = tid & 31;
    const int g    = lane >> 2;    // group id (row within fragment)
    const int tig  = lane & 3;     // thread in group

    float* Ks_hi = sm;
    float* Ks_lo = Ks_hi + SMEM_KV;
    float* Vs_hi = Ks_lo + SMEM_KV;
    float* Vs_lo = Vs_hi + SMEM_KV;
    float* Pw    = Vs_lo + SMEM_KV + w * (16 * P_STRIDE);

    // ---- load Q fragments (scaled), split into tf32 hi/lo ----
    const int qrow0 = bf * L + qt * QT + w * 16;
    const float scale = 0.15811388300841897f;   // 1/sqrt(40)
    uint32_t qa_hi[5][4], qa_lo[5][4];
#pragma unroll
    for (int ks = 0; ks < 5; ks++) {
#pragma unroll
        for (int e = 0; e < 4; e++) {
            int r = g + ((e & 1) ? 8 : 0);
            int c = 8 * ks + tig + ((e & 2) ? 4 : 0);
            float x = Qsrc[(size_t)(qrow0 + r) * C + h * D + c] * scale;
            float lo;
            float hi = tf32_split(x, lo);
            qa_hi[ks][e] = __float_as_uint(hi);
            qa_lo[ks][e] = __float_as_uint(lo);
        }
    }

    float mrow0 = -1e30f, mrow1 = -1e30f;
    float lrow0 = 0.f,    lrow1 = 0.f;
    float o[5][4];
#pragma unroll
    for (int n = 0; n < 5; n++)
#pragma unroll
        for (int e = 0; e < 4; e++) o[n][e] = 0.f;

    for (int kt = 0; kt < L / KT; kt++) {
        __syncthreads();   // all warps done with previous tile's K/V smem
        // ---- cooperative K/V tile load with tf32 hi/lo split ----
        {
            const float* Kg = g_K + (size_t)(kvbase + kt * KT) * C + h * D;
            const float* Vg = g_V + (size_t)(kvbase + kt * KT) * C + h * D;
            for (int e = tid; e < 640; e += 128) {
                int r  = e / 10;
                int c4 = (e - r * 10) * 4;
                float4 kv = *(const float4*)(Kg + (size_t)r * C + c4);
                float4 vv = *(const float4*)(Vg + (size_t)r * C + c4);
                float4 khi, klo, vhi, vlo;
                khi.x = tf32_split(kv.x, klo.x);
                khi.y = tf32_split(kv.y, klo.y);
                khi.z = tf32_split(kv.z, klo.z);
                khi.w = tf32_split(kv.w, klo.w);
                vhi.x = tf32_split(vv.x, vlo.x);
                vhi.y = tf32_split(vv.y, vlo.y);
                vhi.z = tf32_split(vv.z, vlo.z);
                vhi.w = tf32_split(vv.w, vlo.w);
                int off = r * KV_STRIDE + c4;
                *(float4*)(Ks_hi + off) = khi;
                *(float4*)(Ks_lo + off) = klo;
                *(float4*)(Vs_hi + off) = vhi;
                *(float4*)(Vs_lo + off) = vlo;
            }
        }
        __syncthreads();

        // ---- S = (Q*scale) K^T via 3xTF32 ----
        float s[8][4];
#pragma unroll
        for (int n = 0; n < 8; n++) {
            s[n][0] = s[n][1] = s[n][2] = s[n][3] = 0.f;
            const int key = n * 8 + g;
            const float* khp = Ks_hi + key * KV_STRIDE + tig;
            const float* klp = Ks_lo + key * KV_STRIDE + tig;
#pragma unroll
            for (int ks = 0; ks < 5; ks++) {
                uint32_t bh0 = __float_as_uint(khp[8 * ks]);
                uint32_t bh1 = __float_as_uint(khp[8 * ks + 4]);
                uint32_t bl0 = __float_as_uint(klp[8 * ks]);
                uint32_t bl1 = __float_as_uint(klp[8 * ks + 4]);
                mma8(s[n], qa_hi[ks][0], qa_hi[ks][1], qa_hi[ks][2], qa_hi[ks][3], bh0, bh1);
                mma8(s[n], qa_hi[ks][0], qa_hi[ks][1], qa_hi[ks][2], qa_hi[ks][3], bl0, bl1);
                mma8(s[n], qa_lo[ks][0], qa_lo[ks][1], qa_lo[ks][2], qa_lo[ks][3], bh0, bh1);
            }
        }

        // ---- online softmax ----
        float tmax0 = -1e30f, tmax1 = -1e30f;
#pragma unroll
        for (int n = 0; n < 8; n++) {
            tmax0 = fmaxf(tmax0, fmaxf(s[n][0], s[n][1]));
            tmax1 = fmaxf(tmax1, fmaxf(s[n][2], s[n][3]));
        }
        tmax0 = fmaxf(tmax0, __shfl_xor_sync(0xffffffff, tmax0, 1));
        tmax0 = fmaxf(tmax0, __shfl_xor_sync(0xffffffff, tmax0, 2));
        tmax1 = fmaxf(tmax1, __shfl_xor_sync(0xffffffff, tmax1, 1));
        tmax1 = fmaxf(tmax1, __shfl_xor_sync(0xffffffff, tmax1, 2));

        float mn0 = fmaxf(mrow0, tmax0);
        float mn1 = fmaxf(mrow1, tmax1);
        float corr0 = __expf(mrow0 - mn0);
        float corr1 = __expf(mrow1 - mn1);
        mrow0 = mn0; mrow1 = mn1;
        lrow0 *= corr0; lrow1 *= corr1;
#pragma unroll
        for (int n = 0; n < 5; n++) {
            o[n][0] *= corr0; o[n][1] *= corr0;
            o[n][2] *= corr1; o[n][3] *= corr1;
        }

        __syncwarp();   // PV reads of previous Pw finished before overwrite
        float ps0 = 0.f, ps1 = 0.f;
#pragma unroll
        for (int n = 0; n < 8; n++) {
            float p0 = __expf(s[n][0] - mn0);
            float p1 = __expf(s[n][1] - mn0);
            float p2 = __expf(s[n][2] - mn1);
            float p3 = __expf(s[n][3] - mn1);
            ps0 += p0 + p1;
            ps1 += p2 + p3;
            *(float2*)&Pw[g * P_STRIDE + 8 * n + 2 * tig]       = make_float2(p0, p1);
            *(float2*)&Pw[(g + 8) * P_STRIDE + 8 * n + 2 * tig] = make_float2(p2, p3);
        }
        ps0 += __shfl_xor_sync(0xffffffff, ps0, 1);
        ps0 += __shfl_xor_sync(0xffffffff, ps0, 2);
        ps1 += __shfl_xor_sync(0xffffffff, ps1, 1);
        ps1 += __shfl_xor_sync(0xffffffff, ps1, 2);
        lrow0 += ps0; lrow1 += ps1;
        __syncwarp();   // Pw stores visible to whole warp

        // ---- O += P V via 3xTF32 ----
#pragma unroll
        for (int ks2 = 0; ks2 < 8; ks2++) {
            float p0 = Pw[g * P_STRIDE + 8 * ks2 + tig];
            float p1 = Pw[(g + 8) * P_STRIDE + 8 * ks2 + tig];
            float p2 = Pw[g * P_STRIDE + 8 * ks2 + tig + 4];
            float p3 = Pw[(g + 8) * P_STRIDE + 8 * ks2 + tig + 4];
            float l0, l1, l2, l3;
            uint32_t ah0 = __float_as_uint(tf32_split(p0, l0));
            uint32_t ah1 = __float_as_uint(tf32_split(p1, l1));
            uint32_t ah2 = __float_as_uint(tf32_split(p2, l2));
            uint32_t ah3 = __float_as_uint(tf32_split(p3, l3));
            uint32_t al0 = __float_as_uint(l0);
            uint32_t al1 = __float_as_uint(l1);
            uint32_t al2 = __float_as_uint(l2);
            uint32_t al3 = __float_as_uint(l3);
            const float* vh  = Vs_hi + (8 * ks2 + tig) * KV_STRIDE + g;
            const float* vh4 = Vs_hi + (8 * ks2 + tig + 4) * KV_STRIDE + g;
            const float* vl  = Vs_lo + (8 * ks2 + tig) * KV_STRIDE + g;
            const float* vl4 = Vs_lo + (8 * ks2 + tig + 4) * KV_STRIDE + g;
#pragma unroll
            for (int n = 0; n < 5; n++) {
                uint32_t bh0 = __float_as_uint(vh [8 * n]);
                uint32_t bh1 = __float_as_uint(vh4[8 * n]);
                uint32_t bl0 = __float_as_uint(vl [8 * n]);
                uint32_t bl1 = __float_as_uint(vl4[8 * n]);
                mma8(o[n], ah0, ah1, ah2, ah3, bh0, bh1);
                mma8(o[n], ah0, ah1, ah2, ah3, bl0, bl1);
                mma8(o[n], al0, al1, al2, al3, bh0, bh1);
            }
        }
    }

    // ---- epilogue ----
    float inv0 = __fdividef(1.f, lrow0);
    float inv1 = __fdividef(1.f, lrow1);
    float* op0 = O + (size_t)(qrow0 + g)     * C + h * D;
    float* op1 = O + (size_t)(qrow0 + g + 8) * C + h * D;
#pragma unroll
    for (int n = 0; n < 5; n++) {
        *(float2*)(op0 + 8 * n + 2 * tig) = make_float2(o[n][0] * inv0, o[n][1] * inv0);
        *(float2*)(op1 + 8 * n + 2 * tig) = make_float2(o[n][2] * inv1, o[n][3] * inv1);
    }
}

// ============================================================================
// Kernel 3: g_tmp = g_base + g_iat @ Wo_i2v + bo_i2v
// ============================================================================
__global__ __launch_bounds__(256) void ep1_kernel(
    const float* __restrict__ Woi, const float* __restrict__ boi)
{
    __shared__ float As[16][64];
    __shared__ float Bs[16][64];
    int t  = threadIdx.x;
    int m0 = blockIdx.x * 64, n0 = blockIdx.y * 64;
    int ty = t >> 4, tx = t & 15;
    int am = t >> 2, ak = (t & 3) * 4;
    const float* aptr = g_iat + (size_t)(m0 + am) * C;
    int nb = t & 63, kb = t >> 6;

    float acc[4][4];
#pragma unroll
    for (int i = 0; i < 4; i++)
#pragma unroll
        for (int j = 0; j < 4; j++) acc[i][j] = 0.f;

    for (int k0 = 0; k0 < C; k0 += 16) {
        float4 av = *(const float4*)(aptr + k0 + ak);
        As[ak][am] = av.x; As[ak + 1][am] = av.y;
        As[ak + 2][am] = av.z; As[ak + 3][am] = av.w;
#pragma unroll
        for (int i = 0; i < 4; i++)
            Bs[kb + 4 * i][nb] = Woi[(size_t)(k0 + kb + 4 * i) * C + n0 + nb];
        __syncthreads();
#pragma unroll
        for (int kk = 0; kk < 16; kk++) {
            float4 a = *(const float4*)&As[kk][ty * 4];
            float4 b = *(const float4*)&Bs[kk][tx * 4];
            acc[0][0] += a.x * b.x; acc[0][1] += a.x * b.y; acc[0][2] += a.x * b.z; acc[0][3] += a.x * b.w;
            acc[1][0] += a.y * b.x; acc[1][1] += a.y * b.y; acc[1][2] += a.y * b.z; acc[1][3] += a.y * b.w;
            acc[2][0] += a.z * b.x; acc[2][1] += a.z * b.y; acc[2][2] += a.z * b.z; acc[2][3] += a.z * b.w;
            acc[3][0] += a.w * b.x; acc[3][1] += a.w * b.y; acc[3][2] += a.w * b.z; acc[3][3] += a.w * b.w;
        }
        __syncthreads();
    }
    int gn = n0 + tx * 4;
    float4 bv = *(const float4*)&boi[gn];
#pragma unroll
    for (int i = 0; i < 4; i++) {
        int gm = m0 + ty * 4 + i;
        float4 ad = *(const float4*)&g_base[(size_t)gm * C + gn];
        float4 v = make_float4(acc[i][0] + ad.x + bv.x,
                               acc[i][1] + ad.y + bv.y,
                               acc[i][2] + ad.z + bv.z,
                               acc[i][3] + ad.w + bv.w);
        *(float4*)&g_tmp[(size_t)gm * C + gn] = v;
    }
}

// ============================================================================
// Kernel 4: out = g_tmp @ Wo + bo, scattered back to (b n f) l c layout.
// ============================================================================
__global__ __launch_bounds__(256) void ep2_kernel(
    const float* __restrict__ Wo, const float* __restrict__ bo,
    float* __restrict__ out)
{
    __shared__ float As[16][64];
    __shared__ float Bs[16][64];
    int t  = threadIdx.x;
    int m0 = blockIdx.x * 64, n0 = blockIdx.y * 64;
    int ty = t >> 4, tx = t & 15;
    int am = t >> 2, ak = (t & 3) * 4;
    const float* aptr = g_tmp + (size_t)(m0 + am) * C;
    int nb = t & 63, kb = t >> 6;

    float acc[4][4];
#pragma unroll
    for (int i = 0; i < 4; i++)
#pragma unroll
        for (int j = 0; j < 4; j++) acc[i][j] = 0.f;

    for (int k0 = 0; k0 < C; k0 += 16) {
        float4 av = *(const float4*)(aptr + k0 + ak);
        As[ak][am] = av.x; As[ak + 1][am] = av.y;
        As[ak + 2][am] = av.z; As[ak + 3][am] = av.w;
#pragma unroll
        for (int i = 0; i < 4; i++)
            Bs[kb + 4 * i][nb] = Wo[(size_t)(k0 + kb + 4 * i) * C + n0 + nb];
        __syncthreads();
#pragma unroll
        for (int kk = 0; kk < 16; kk++) {
            float4 a = *(const float4*)&As[kk][ty * 4];
            float4 b = *(const float4*)&Bs[kk][tx * 4];
            acc[0][0] += a.x * b.x; acc[0][1] += a.x * b.y; acc[0][2] += a.x * b.z; acc[0][3] += a.x * b.w;
            acc[1][0] += a.y * b.x; acc[1][1] += a.y * b.y; acc[1][2] += a.y * b.z; acc[1][3] += a.y * b.w;
            acc[2][0] += a.z * b.x; acc[2][1] += a.z * b.y; acc[2][2] += a.z * b.z; acc[2][3] += a.z * b.w;
            acc[3][0] += a.w * b.x; acc[3][1] += a.w * b.y; acc[3][2] += a.w * b.z; acc[3][3] += a.w * b.w;
        }
        __syncthreads();
    }
    int gn = n0 + tx * 4;
    float4 bv = *(const float4*)&bo[gn];
#pragma unroll
    for (int i = 0; i < 4; i++) {
        int gm = m0 + ty * 4 + i;
        int orow = hidden_row(gm);  // inverse rearrange on store
        float4 v = make_float4(acc[i][0] + bv.x, acc[i][1] + bv.y,
                               acc[i][2] + bv.z, acc[i][3] + bv.w);
        *(float4*)&out[(size_t)orow * C + gn] = v;
    }
}

// ============================================================================
extern "C" void kernel_launch(void* const* d_in, const int* in_sizes, int n_in,
                              void* d_out, int out_size)
{
    const float* hidden = (const float*)d_in[0];
    const float* Wq  = (const float*)d_in[1];
    const float* Wk  = (const float*)d_in[2];
    const float* Wv  = (const float*)d_in[3];
    const float* Wo  = (const float*)d_in[4];
    const float* bo  = (const float*)d_in[5];
    const float* Wqi = (const float*)d_in[6];
    const float* Woi = (const float*)d_in[7];
    const float* boi = (const float*)d_in[8];
    float* out = (float*)d_out;

    // 1) Q, K, V, Q_i2v projections (gathered A)
    proj_kernel<<<dim3(ROWS / 64, C / 64, 4), 256>>>(hidden, Wq, Wk, Wv, Wqi);

    // 2) both attentions in one launch (z: bf 0-7 = base, 8-15 = i2v)
    cudaFuncSetAttribute(attn_mma_kernel,
                         cudaFuncAttributeMaxDynamicSharedMemorySize, SMEM_ATTN);
    attn_mma_kernel<<<dim3(L / QT, H, 2 * BFRM), 128, SMEM_ATTN>>>();

    // 3) tmp = base + i2v @ Wo_i2v + bo_i2v
    ep1_kernel<<<dim3(ROWS / 64, C / 64), 256>>>(Woi, boi);
    // 4) out = tmp @ Wo + bo (scatter to output layout)
    ep2_kernel<<<dim3(ROWS / 64, C / 64), 256>>>(Wo, bo, out);
}

// round 3
// speedup vs baseline: 2.0718x; 2.0718x over previous
#include <cuda_runtime.h>
#include <cstdint>

// Problem constants: b=1, n=4 views, f=8 frames, l=256, C=320, H=8, D=40.
#define C       320
#define L       1024
#define H       8
#define D       40
#define BFRM    8
#define ROWS    (BFRM * L)   // 8192

// ---- scratch (no allocations allowed) ----
__device__ float g_Q   [ROWS * C];
__device__ float g_K   [ROWS * C];
__device__ float g_V   [ROWS * C];
__device__ float g_Qi  [ROWS * C];
__device__ float g_base[ROWS * C];
__device__ float g_iat [ROWS * C];
__device__ float g_tmp [ROWS * C];

// logical row (bf*1024 + n*256 + l) -> hidden row ((n*8+bf)*256 + l)
__device__ __forceinline__ int hidden_row(int g) {
    int bf = g >> 10;
    int r  = g & 1023;
    int n  = r >> 8;
    int l  = r & 255;
    return ((n << 3) + bf) * 256 + l;
}

// ============================================================================
// tf32 helpers
// ============================================================================
__device__ __forceinline__ uint32_t tf32_of(float x) {
    uint32_t r;
    asm("cvt.rna.tf32.f32 %0, %1;" : "=r"(r) : "f"(x));
    return r;
}

__device__ __forceinline__ void mma8(float d[4],
                                     uint32_t a0, uint32_t a1, uint32_t a2, uint32_t a3,
                                     uint32_t b0, uint32_t b1) {
    asm volatile(
        "mma.sync.aligned.m16n8k8.row.col.f32.tf32.tf32.f32 "
        "{%0,%1,%2,%3}, {%4,%5,%6,%7}, {%8,%9}, {%0,%1,%2,%3};"
        : "+f"(d[0]), "+f"(d[1]), "+f"(d[2]), "+f"(d[3])
        : "r"(a0), "r"(a1), "r"(a2), "r"(a3), "r"(b0), "r"(b1));
}

// ============================================================================
// Kernel 1: fused projection GEMM (Q, K, V, Q_i2v). 64x64 tile, BK=16.
// K and V outputs are pre-rounded to tf32 (consumed only by tensor cores).
// ============================================================================
__global__ __launch_bounds__(256) void proj_kernel(
    const float* __restrict__ hidden,
    const float* __restrict__ Wq, const float* __restrict__ Wk,
    const float* __restrict__ Wv, const float* __restrict__ Wqi)
{
    const float* W;
    float* Y;
    bool round_tf32 = false;
    switch (blockIdx.z) {
        case 0:  W = Wq;  Y = g_Q;  break;
        case 1:  W = Wk;  Y = g_K;  round_tf32 = true; break;
        case 2:  W = Wv;  Y = g_V;  round_tf32 = true; break;
        default: W = Wqi; Y = g_Qi; break;
    }
    __shared__ float As[16][64];
    __shared__ float Bs[16][64];
    int t  = threadIdx.x;
    int m0 = blockIdx.x * 64, n0 = blockIdx.y * 64;
    int ty = t >> 4, tx = t & 15;
    int am = t >> 2, ak = (t & 3) * 4;
    const float* aptr = hidden + (size_t)hidden_row(m0 + am) * C;
    int nb = t & 63, kb = t >> 6;

    float acc[4][4];
#pragma unroll
    for (int i = 0; i < 4; i++)
#pragma unroll
        for (int j = 0; j < 4; j++) acc[i][j] = 0.f;

    for (int k0 = 0; k0 < C; k0 += 16) {
        float4 av = *(const float4*)(aptr + k0 + ak);
        As[ak    ][am] = av.x;
        As[ak + 1][am] = av.y;
        As[ak + 2][am] = av.z;
        As[ak + 3][am] = av.w;
#pragma unroll
        for (int i = 0; i < 4; i++)
            Bs[kb + 4 * i][nb] = W[(size_t)(k0 + kb + 4 * i) * C + n0 + nb];
        __syncthreads();
#pragma unroll
        for (int kk = 0; kk < 16; kk++) {
            float4 a = *(const float4*)&As[kk][ty * 4];
            float4 b = *(const float4*)&Bs[kk][tx * 4];
            acc[0][0] += a.x * b.x; acc[0][1] += a.x * b.y; acc[0][2] += a.x * b.z; acc[0][3] += a.x * b.w;
            acc[1][0] += a.y * b.x; acc[1][1] += a.y * b.y; acc[1][2] += a.y * b.z; acc[1][3] += a.y * b.w;
            acc[2][0] += a.z * b.x; acc[2][1] += a.z * b.y; acc[2][2] += a.z * b.z; acc[2][3] += a.z * b.w;
            acc[3][0] += a.w * b.x; acc[3][1] += a.w * b.y; acc[3][2] += a.w * b.z; acc[3][3] += a.w * b.w;
        }
        __syncthreads();
    }
#pragma unroll
    for (int i = 0; i < 4; i++) {
        float4 v = make_float4(acc[i][0], acc[i][1], acc[i][2], acc[i][3]);
        if (round_tf32) {
            v.x = __uint_as_float(tf32_of(v.x));
            v.y = __uint_as_float(tf32_of(v.y));
            v.z = __uint_as_float(tf32_of(v.z));
            v.w = __uint_as_float(tf32_of(v.w));
        }
        *(float4*)&Y[(size_t)(m0 + ty * 4 + i) * C + n0 + tx * 4] = v;
    }
}

// ============================================================================
// Kernel 2: flash attention, single-pass tf32 mma.
// One launch covers base (i2v=0) and i2v (i2v=1) attention.
// Block: 128 thr = 4 warps, each warp 16 q-rows -> 64 q-rows/block.
// Key tiles of 64; K/V in smem already tf32-rounded (done by proj).
// ============================================================================
#define KT        64
#define QT        64
#define KV_STRIDE 44   // floats per K/V smem row
#define P_STRIDE  66   // floats per P smem row
#define SMEM_KV   (KT * KV_STRIDE)                           // 2816 floats
#define SMEM_ATTN ((2 * SMEM_KV + 4 * 16 * P_STRIDE) * 4)    // 39424 bytes

__global__ __launch_bounds__(128) void attn_mma_kernel()
{
    extern __shared__ float sm[];
    const int i2v = blockIdx.z >> 3;
    const int bf  = blockIdx.z & 7;
    const int h   = blockIdx.y;
    const int qt  = blockIdx.x;

    const float* Qsrc = i2v ? g_Qi : g_Q;
    float*       O    = i2v ? g_iat : g_base;
    const int kvbase  = i2v ? 0 : bf * L;

    const int tid  = threadIdx.x;
    const int w    = tid >> 5;
    const int lane = tid & 31;
    const int g    = lane >> 2;    // row within fragment
    const int tig  = lane & 3;     // thread in group

    float* Ks = sm;
    float* Vs = Ks + SMEM_KV;
    float* Pw = Vs + SMEM_KV + w * (16 * P_STRIDE);

    // ---- load Q fragments (scaled), round to tf32 ----
    const int qrow0 = bf * L + qt * QT + w * 16;
    const float scale = 0.15811388300841897f;   // 1/sqrt(40)
    uint32_t qa[5][4];
#pragma unroll
    for (int ks = 0; ks < 5; ks++) {
#pragma unroll
        for (int e = 0; e < 4; e++) {
            int r = g + ((e & 1) ? 8 : 0);
            int c = 8 * ks + tig + ((e & 2) ? 4 : 0);
            float x = Qsrc[(size_t)(qrow0 + r) * C + h * D + c] * scale;
            qa[ks][e] = tf32_of(x);
        }
    }

    float mrow0 = -1e30f, mrow1 = -1e30f;
    float lrow0 = 0.f,    lrow1 = 0.f;
    float o[5][4];
#pragma unroll
    for (int n = 0; n < 5; n++)
#pragma unroll
        for (int e = 0; e < 4; e++) o[n][e] = 0.f;

    for (int kt = 0; kt < L / KT; kt++) {
        __syncthreads();   // all warps done with previous tile's K/V smem
        // ---- cooperative K/V tile load (already tf32-rounded in global) ----
        {
            const float* Kg = g_K + (size_t)(kvbase + kt * KT) * C + h * D;
            const float* Vg = g_V + (size_t)(kvbase + kt * KT) * C + h * D;
            for (int e = tid; e < 640; e += 128) {
                int r  = e / 10;
                int c4 = (e - r * 10) * 4;
                int off = r * KV_STRIDE + c4;
                *(float4*)(Ks + off) = *(const float4*)(Kg + (size_t)r * C + c4);
                *(float4*)(Vs + off) = *(const float4*)(Vg + (size_t)r * C + c4);
            }
        }
        __syncthreads();

        // ---- S = (Q*scale) K^T ----
        float s[8][4];
#pragma unroll
        for (int n = 0; n < 8; n++) {
            s[n][0] = s[n][1] = s[n][2] = s[n][3] = 0.f;
            const int key = n * 8 + g;
            const float* kp = Ks + key * KV_STRIDE + tig;
#pragma unroll
            for (int ks = 0; ks < 5; ks++) {
                uint32_t b0 = __float_as_uint(kp[8 * ks]);
                uint32_t b1 = __float_as_uint(kp[8 * ks + 4]);
                mma8(s[n], qa[ks][0], qa[ks][1], qa[ks][2], qa[ks][3], b0, b1);
            }
        }

        // ---- online softmax ----
        float tmax0 = -1e30f, tmax1 = -1e30f;
#pragma unroll
        for (int n = 0; n < 8; n++) {
            tmax0 = fmaxf(tmax0, fmaxf(s[n][0], s[n][1]));
            tmax1 = fmaxf(tmax1, fmaxf(s[n][2], s[n][3]));
        }
        tmax0 = fmaxf(tmax0, __shfl_xor_sync(0xffffffff, tmax0, 1));
        tmax0 = fmaxf(tmax0, __shfl_xor_sync(0xffffffff, tmax0, 2));
        tmax1 = fmaxf(tmax1, __shfl_xor_sync(0xffffffff, tmax1, 1));
        tmax1 = fmaxf(tmax1, __shfl_xor_sync(0xffffffff, tmax1, 2));

        float mn0 = fmaxf(mrow0, tmax0);
        float mn1 = fmaxf(mrow1, tmax1);
        float corr0 = __expf(mrow0 - mn0);
        float corr1 = __expf(mrow1 - mn1);
        mrow0 = mn0; mrow1 = mn1;
        lrow0 *= corr0; lrow1 *= corr1;
#pragma unroll
        for (int n = 0; n < 5; n++) {
            o[n][0] *= corr0; o[n][1] *= corr0;
            o[n][2] *= corr1; o[n][3] *= corr1;
        }

        __syncwarp();   // PV reads of previous Pw finished before overwrite
        float ps0 = 0.f, ps1 = 0.f;
#pragma unroll
        for (int n = 0; n < 8; n++) {
            float p0 = __expf(s[n][0] - mn0);
            float p1 = __expf(s[n][1] - mn0);
            float p2 = __expf(s[n][2] - mn1);
            float p3 = __expf(s[n][3] - mn1);
            ps0 += p0 + p1;
            ps1 += p2 + p3;
            // store tf32-rounded (consumed as mma A operand)
            p0 = __uint_as_float(tf32_of(p0));
            p1 = __uint_as_float(tf32_of(p1));
            p2 = __uint_as_float(tf32_of(p2));
            p3 = __uint_as_float(tf32_of(p3));
            *(float2*)&Pw[g * P_STRIDE + 8 * n + 2 * tig]       = make_float2(p0, p1);
            *(float2*)&Pw[(g + 8) * P_STRIDE + 8 * n + 2 * tig] = make_float2(p2, p3);
        }
        ps0 += __shfl_xor_sync(0xffffffff, ps0, 1);
        ps0 += __shfl_xor_sync(0xffffffff, ps0, 2);
        ps1 += __shfl_xor_sync(0xffffffff, ps1, 1);
        ps1 += __shfl_xor_sync(0xffffffff, ps1, 2);
        lrow0 += ps0; lrow1 += ps1;
        __syncwarp();   // Pw stores visible to whole warp

        // ---- O += P V ----
#pragma unroll
        for (int ks2 = 0; ks2 < 8; ks2++) {
            uint32_t a0 = __float_as_uint(Pw[g * P_STRIDE + 8 * ks2 + tig]);
            uint32_t a1 = __float_as_uint(Pw[(g + 8) * P_STRIDE + 8 * ks2 + tig]);
            uint32_t a2 = __float_as_uint(Pw[g * P_STRIDE + 8 * ks2 + tig + 4]);
            uint32_t a3 = __float_as_uint(Pw[(g + 8) * P_STRIDE + 8 * ks2 + tig + 4]);
            const float* vp  = Vs + (8 * ks2 + tig) * KV_STRIDE + g;
            const float* vp4 = Vs + (8 * ks2 + tig + 4) * KV_STRIDE + g;
#pragma unroll
            for (int n = 0; n < 5; n++) {
                uint32_t b0 = __float_as_uint(vp [8 * n]);
                uint32_t b1 = __float_as_uint(vp4[8 * n]);
                mma8(o[n], a0, a1, a2, a3, b0, b1);
            }
        }
    }

    // ---- epilogue ----
    float inv0 = __fdividef(1.f, lrow0);
    float inv1 = __fdividef(1.f, lrow1);
    float* op0 = O + (size_t)(qrow0 + g)     * C + h * D;
    float* op1 = O + (size_t)(qrow0 + g + 8) * C + h * D;
#pragma unroll
    for (int n = 0; n < 5; n++) {
        *(float2*)(op0 + 8 * n + 2 * tig) = make_float2(o[n][0] * inv0, o[n][1] * inv0);
        *(float2*)(op1 + 8 * n + 2 * tig) = make_float2(o[n][2] * inv1, o[n][3] * inv1);
    }
}

// ============================================================================
// Kernel 3: g_tmp = g_base + g_iat @ Wo_i2v + bo_i2v
// ============================================================================
__global__ __launch_bounds__(256) void ep1_kernel(
    const float* __restrict__ Woi, const float* __restrict__ boi)
{
    __shared__ float As[16][64];
    __shared__ float Bs[16][64];
    int t  = threadIdx.x;
    int m0 = blockIdx.x * 64, n0 = blockIdx.y * 64;
    int ty = t >> 4, tx = t & 15;
    int am = t >> 2, ak = (t & 3) * 4;
    const float* aptr = g_iat + (size_t)(m0 + am) * C;
    int nb = t & 63, kb = t >> 6;

    float acc[4][4];
#pragma unroll
    for (int i = 0; i < 4; i++)
#pragma unroll
        for (int j = 0; j < 4; j++) acc[i][j] = 0.f;

    for (int k0 = 0; k0 < C; k0 += 16) {
        float4 av = *(const float4*)(aptr + k0 + ak);
        As[ak][am] = av.x; As[ak + 1][am] = av.y;
        As[ak + 2][am] = av.z; As[ak + 3][am] = av.w;
#pragma unroll
        for (int i = 0; i < 4; i++)
            Bs[kb + 4 * i][nb] = Woi[(size_t)(k0 + kb + 4 * i) * C + n0 + nb];
        __syncthreads();
#pragma unroll
        for (int kk = 0; kk < 16; kk++) {
            float4 a = *(const float4*)&As[kk][ty * 4];
            float4 b = *(const float4*)&Bs[kk][tx * 4];
            acc[0][0] += a.x * b.x; acc[0][1] += a.x * b.y; acc[0][2] += a.x * b.z; acc[0][3] += a.x * b.w;
            acc[1][0] += a.y * b.x; acc[1][1] += a.y * b.y; acc[1][2] += a.y * b.z; acc[1][3] += a.y * b.w;
            acc[2][0] += a.z * b.x; acc[2][1] += a.z * b.y; acc[2][2] += a.z * b.z; acc[2][3] += a.z * b.w;
            acc[3][0] += a.w * b.x; acc[3][1] += a.w * b.y; acc[3][2] += a.w * b.z; acc[3][3] += a.w * b.w;
        }
        __syncthreads();
    }
    int gn = n0 + tx * 4;
    float4 bv = *(const float4*)&boi[gn];
#pragma unroll
    for (int i = 0; i < 4; i++) {
        int gm = m0 + ty * 4 + i;
        float4 ad = *(const float4*)&g_base[(size_t)gm * C + gn];
        float4 v = make_float4(acc[i][0] + ad.x + bv.x,
                               acc[i][1] + ad.y + bv.y,
                               acc[i][2] + ad.z + bv.z,
                               acc[i][3] + ad.w + bv.w);
        *(float4*)&g_tmp[(size_t)gm * C + gn] = v;
    }
}

// ============================================================================
// Kernel 4: out = g_tmp @ Wo + bo, scattered back to (b n f) l c layout.
// ============================================================================
__global__ __launch_bounds__(256) void ep2_kernel(
    const float* __restrict__ Wo, const float* __restrict__ bo,
    float* __restrict__ out)
{
    __shared__ float As[16][64];
    __shared__ float Bs[16][64];
    int t  = threadIdx.x;
    int m0 = blockIdx.x * 64, n0 = blockIdx.y * 64;
    int ty = t >> 4, tx = t & 15;
    int am = t >> 2, ak = (t & 3) * 4;
    const float* aptr = g_tmp + (size_t)(m0 + am) * C;
    int nb = t & 63, kb = t >> 6;

    float acc[4][4];
#pragma unroll
    for (int i = 0; i < 4; i++)
#pragma unroll
        for (int j = 0; j < 4; j++) acc[i][j] = 0.f;

    for (int k0 = 0; k0 < C; k0 += 16) {
        float4 av = *(const float4*)(aptr + k0 + ak);
        As[ak][am] = av.x; As[ak + 1][am] = av.y;
        As[ak + 2][am] = av.z; As[ak + 3][am] = av.w;
#pragma unroll
        for (int i = 0; i < 4; i++)
            Bs[kb + 4 * i][nb] = Wo[(size_t)(k0 + kb + 4 * i) * C + n0 + nb];
        __syncthreads();
#pragma unroll
        for (int kk = 0; kk < 16; kk++) {
            float4 a = *(const float4*)&As[kk][ty * 4];
            float4 b = *(const float4*)&Bs[kk][tx * 4];
            acc[0][0] += a.x * b.x; acc[0][1] += a.x * b.y; acc[0][2] += a.x * b.z; acc[0][3] += a.x * b.w;
            acc[1][0] += a.y * b.x; acc[1][1] += a.y * b.y; acc[1][2] += a.y * b.z; acc[1][3] += a.y * b.w;
            acc[2][0] += a.z * b.x; acc[2][1] += a.z * b.y; acc[2][2] += a.z * b.z; acc[2][3] += a.z * b.w;
            acc[3][0] += a.w * b.x; acc[3][1] += a.w * b.y; acc[3][2] += a.w * b.z; acc[3][3] += a.w * b.w;
        }
        __syncthreads();
    }
    int gn = n0 + tx * 4;
    float4 bv = *(const float4*)&bo[gn];
#pragma unroll
    for (int i = 0; i < 4; i++) {
        int gm = m0 + ty * 4 + i;
        int orow = hidden_row(gm);  // inverse rearrange on store
        float4 v = make_float4(acc[i][0] + bv.x, acc[i][1] + bv.y,
                               acc[i][2] + bv.z, acc[i][3] + bv.w);
        *(float4*)&out[(size_t)orow * C + gn] = v;
    }
}

// ============================================================================
extern "C" void kernel_launch(void* const* d_in, const int* in_sizes, int n_in,
                              void* d_out, int out_size)
{
    const float* hidden = (const float*)d_in[0];
    const float* Wq  = (const float*)d_in[1];
    const float* Wk  = (const float*)d_in[2];
    const float* Wv  = (const float*)d_in[3];
    const float* Wo  = (const float*)d_in[4];
    const float* bo  = (const float*)d_in[5];
    const float* Wqi = (const float*)d_in[6];
    const float* Woi = (const float*)d_in[7];
    const float* boi = (const float*)d_in[8];
    float* out = (float*)d_out;

    // 1) Q, K, V, Q_i2v projections (K/V tf32-rounded)
    proj_kernel<<<dim3(ROWS / 64, C / 64, 4), 256>>>(hidden, Wq, Wk, Wv, Wqi);

    // 2) both attentions in one launch (z: bf 0-7 = base, 8-15 = i2v)
    cudaFuncSetAttribute(attn_mma_kernel,
                         cudaFuncAttributeMaxDynamicSharedMemorySize, SMEM_ATTN);
    attn_mma_kernel<<<dim3(L / QT, H, 2 * BFRM), 128, SMEM_ATTN>>>();

    // 3) tmp = base + i2v @ Wo_i2v + bo_i2v
    ep1_kernel<<<dim3(ROWS / 64, C / 64), 256>>>(Woi, boi);
    // 4) out = tmp @ Wo + bo (scatter to output layout)
    ep2_kernel<<<dim3(ROWS / 64, C / 64), 256>>>(Wo, bo, out);
}